// round 13
// baseline (speedup 1.0000x reference)
#include <cuda_runtime.h>
#include <cuda_bf16.h>
#include <math.h>

#define N_ROWS 8192
#define D_DIM  128
#define PART_VBLOCKS 1024
#define GRID 592           // 148 SMs x 4 resident blocks: single wave guaranteed
#define PB 24              // smem pitch in bf16 (48B): conflict-free frag loads

// ---------------- device scratch ----------------
__device__ __nv_bfloat16 d_Ebf[2][N_ROWS * 16];    // bf16 screen rows: 14 dims + 2 aux
__device__ int           d_idx[2][N_ROWS];         // compacted -> original row
__device__ float         d_rsq[2][N_ROWS];         // full ||x||^2 (compacted order)
__device__ unsigned long long d_cnt64;             // packed counts lo=c0, hi=c1
__device__ float         d_vsum[2][D_DIM];
__device__ float4        d_part[PART_VBLOCKS];     // {focal, graph, sn0, sn1}
__device__ double        d_cross;
__device__ unsigned      d_sync1;                  // phase barrier
__device__ unsigned      d_done;                   // finalize ticket

struct SmemP {
    float v[8][D_DIM];
    float g[8][D_DIM];
    float sn[2];
    float focal, graph;
    int   lab[8];
    int   base[2];
};
struct SmemC {
    __nv_bfloat16 A[128 * PB];
    __nv_bfloat16 B[128 * PB];
    float    redw[8];
    unsigned ticket;
    double   sd[4][8];
    double   s[256];
};

__device__ __forceinline__ float warp_sum(float v) {
    #pragma unroll
    for (int o = 16; o > 0; o >>= 1) v += __shfl_xor_sync(0xffffffffu, v, o);
    return v;
}
__device__ __forceinline__ double warp_sum_d(double v) {
    #pragma unroll
    for (int o = 16; o > 0; o >>= 1) v += __shfl_xor_sync(0xffffffffu, v, o);
    return v;
}

// exact fp32 recheck via original-row indices; never touches mma regs
__device__ __noinline__ float rare_pair(const float* __restrict__ feat,
                                        int gi, int gj) {
    const float* A = feat + (size_t)d_idx[0][gi] * D_DIM;
    const float* B = feat + (size_t)d_idx[1][gj] * D_DIM;
    float dot = 0.0f;
    #pragma unroll 4
    for (int d = 0; d < D_DIM; ++d) dot += A[d] * B[d];
    float sq = fmaxf(d_rsq[0][gi] + d_rsq[1][gj] - 2.0f * dot, 0.0f);
    float t = 1.0f - sqrtf(sq);
    return (t > 0.0f) ? t * t : 0.0f;
}

// ---------------- fused persistent kernel ----------------
__global__ void __launch_bounds__(256, 4) fused_kernel(
    const float* __restrict__ preds,
    const float* __restrict__ targets,
    const float* __restrict__ features,
    const float* __restrict__ gfeat,
    float* __restrict__ out)
{
    __shared__ union { SmemP p; SmemC c; } sm;

    int tid = threadIdx.x;
    int bid = blockIdx.x;
    int warp = tid >> 5, lane = tid & 31;

    // ================= phase 1: partition (2 virtual blocks each) ===========
    for (int vb = bid; vb < PART_VBLOCKS; vb += GRID) {
        if (tid == 254) { sm.p.sn[0] = 0.0f; sm.p.sn[1] = 0.0f; }
        if (tid == 255) { sm.p.focal = 0.0f; sm.p.graph = 0.0f; }

        int i = vb * 8 + warp;

        float4 f = *(const float4*)(features + (size_t)i * D_DIM + lane * 4);
        float c  = f.x*f.x + f.y*f.y + f.z*f.z + f.w*f.w;
        float nsq   = warp_sum(c);
        float c14 = (lane < 3) ? c : ((lane == 3) ? (f.x*f.x + f.y*f.y) : 0.0f);
        float nsq14 = warp_sum(c14);

        float4 ga = *(const float4*)(gfeat + (size_t)i * D_DIM + lane * 4);

        float tgt = targets[i];
        int lab = (tgt > 0.5f) ? 1 : 0;
        if (lane == 0) sm.p.lab[warp] = lab;

        sm.p.v[warp][lane * 4 + 0] = f.x;
        sm.p.v[warp][lane * 4 + 1] = f.y;
        sm.p.v[warp][lane * 4 + 2] = f.z;
        sm.p.v[warp][lane * 4 + 3] = f.w;
        *(float4*)&sm.p.g[warp][lane * 4] = ga;
        __syncthreads();

        if (tid == 0) {
            int c1 = 0;
            #pragma unroll
            for (int w = 0; w < 8; ++w) c1 += sm.p.lab[w];
            unsigned long long add = ((unsigned long long)c1 << 32)
                                   | (unsigned long long)(8 - c1);
            unsigned long long old = atomicAdd(&d_cnt64, add);
            sm.p.base[0] = (int)(old & 0xffffffffull);
            sm.p.base[1] = (int)(old >> 32);
        }
        __syncthreads();

        int rank = 0;
        #pragma unroll
        for (int w = 0; w < 8; ++w) rank += (w < warp && sm.p.lab[w] == lab);
        int idx = sm.p.base[lab] + rank;

        if (lane == 0) { d_idx[lab][idx] = i; d_rsq[lab][idx] = nsq; }

        {   // bf16 screen row: dims0-13 = +/-sqrt2*x, dims14-15 aux
            float s = (lab == 0) ? -1.41421356237f : 1.41421356237f;
            __nv_bfloat16* E = d_Ebf[lab] + (size_t)idx * 16;
            if (lane < 3) {
                __nv_bfloat162 p0 = __floats2bfloat162_rn(s*f.x, s*f.y);
                __nv_bfloat162 p1 = __floats2bfloat162_rn(s*f.z, s*f.w);
                *(__nv_bfloat162*)(E + lane * 4)     = p0;
                *(__nv_bfloat162*)(E + lane * 4 + 2) = p1;
            } else if (lane == 3) {
                __nv_bfloat162 p0 = __floats2bfloat162_rn(s*f.x, s*f.y); // 12,13
                __nv_bfloat16 nb  = __float2bfloat16(nsq14);
                __nv_bfloat16 one = __float2bfloat16(1.0f);
                __nv_bfloat162 aux = (lab == 0) ? __halves2bfloat162(nb, one)
                                                : __halves2bfloat162(one, nb);
                *(__nv_bfloat162*)(E + 12) = p0;
                *(__nv_bfloat162*)(E + 14) = aux;
            }
        }

        if (lane == 0) atomicAdd(&sm.p.sn[lab], nsq);
        if (lane == 0) {
            float p = preds[i];
            float bce = fmaxf(p, 0.0f) - p * tgt + log1pf(expf(-fabsf(p)));
            float pt = expf(-bce);
            float om = 1.0f - pt;
            atomicAdd(&sm.p.focal, 0.25f * om * om * bce);
        }

        if (i >= 1) {
            float4 gb;
            if (warp == 0)
                gb = *(const float4*)(gfeat + (size_t)(i - 1) * D_DIM + lane * 4);
            else
                gb = *(const float4*)&sm.p.g[warp - 1][lane * 4];
            float dx = ga.x - gb.x, dy = ga.y - gb.y;
            float dz = ga.z - gb.z, dw = ga.w - gb.w;
            float ds = warp_sum(dx*dx + dy*dy + dz*dz + dw*dw);
            if (lane == 0) atomicAdd(&sm.p.graph, sqrtf(ds));
        }
        __syncthreads();

        {
            int cls = tid >> 7, comp = tid & 127;
            float sum = 0.0f;
            #pragma unroll
            for (int w = 0; w < 8; ++w)
                if (sm.p.lab[w] == cls) sum += sm.p.v[w][comp];
            if (sum != 0.0f) atomicAdd(&d_vsum[cls][comp], sum);
        }
        if (tid == 0)
            d_part[vb] = make_float4(sm.p.focal, sm.p.graph, sm.p.sn[0], sm.p.sn[1]);
        __syncthreads();   // before next iteration re-inits shared
    }

    // ================= global barrier (all 592 blocks resident) =============
    if (tid == 0) {
        __threadfence();
        unsigned v = atomicAdd(&d_sync1, 1u) + 1u;
        while (v < GRID) { __nanosleep(128); v = *(volatile unsigned*)&d_sync1; }
        __threadfence();
    }
    __syncthreads();

    // ================= phase 2: cross screen via bf16 HMMA ==================
    unsigned long long cnt = d_cnt64;
    int n0 = (int)(cnt & 0xffffffffull);
    int n1 = (int)(cnt >> 32);
    int tiles_r = (n0 + 127) >> 7;
    int tiles_c = (n1 + 127) >> 7;
    int ntiles = tiles_r * tiles_c;

    float lsum = 0.0f;

    int wid = tid >> 5;
    int g = lane >> 2, t = lane & 3;
    int r0 = (wid & 3) * 32;
    int c0 = (wid >> 2) * 64;
    int ldr = tid >> 1, ldh = tid & 1;
    const uint4 pad = make_uint4(0u, 0u, 0u, 0u);
    const uint4 padaux = make_uint4(0u, 0u, 0u, 0x71157115u);

    for (int tile = bid; tile < ntiles; tile += GRID) {
        int tr = tile / tiles_c;
        int tc = tile - tr * tiles_c;
        int row0 = tr * 128, col0 = tc * 128;

        uint4 va = ldh ? padaux : pad;
        if (row0 + ldr < n0)
            va = *((const uint4*)(d_Ebf[0] + (size_t)(row0 + ldr) * 16) + ldh);
        uint4 vb4 = ldh ? padaux : pad;
        if (col0 + ldr < n1)
            vb4 = *((const uint4*)(d_Ebf[1] + (size_t)(col0 + ldr) * 16) + ldh);
        *(uint4*)(sm.c.A + ldr * PB + ldh * 8) = va;
        *(uint4*)(sm.c.B + ldr * PB + ldh * 8) = vb4;
        __syncthreads();

        unsigned a[2][4];
        #pragma unroll
        for (int rb = 0; rb < 2; ++rb) {
            const __nv_bfloat16* base = sm.c.A + (r0 + rb * 16 + g) * PB + t * 2;
            a[rb][0] = *(const unsigned*)(base);
            a[rb][1] = *(const unsigned*)(base + 8 * PB);
            a[rb][2] = *(const unsigned*)(base + 8);
            a[rb][3] = *(const unsigned*)(base + 8 * PB + 8);
        }

        unsigned fmask = 0u;
        #pragma unroll
        for (int cb = 0; cb < 8; ++cb) {
            const __nv_bfloat16* bb = sm.c.B + (c0 + cb * 8 + g) * PB + t * 2;
            unsigned b0 = *(const unsigned*)(bb);
            unsigned b1 = *(const unsigned*)(bb + 8);
            #pragma unroll
            for (int rb = 0; rb < 2; ++rb) {
                float d0, d1, d2, d3;
                asm("mma.sync.aligned.m16n8k16.row.col.f32.bf16.bf16.f32 "
                    "{%0,%1,%2,%3},{%4,%5,%6,%7},{%8,%9},{%10,%10,%10,%10};"
                    : "=f"(d0), "=f"(d1), "=f"(d2), "=f"(d3)
                    : "r"(a[rb][0]), "r"(a[rb][1]), "r"(a[rb][2]), "r"(a[rb][3]),
                      "r"(b0), "r"(b1), "f"(0.0f));
                float mn = fminf(fminf(d0, d1), fminf(d2, d3));
                if (mn < 1.5f) fmask |= 1u << (cb * 2 + rb);
            }
        }

        if (fmask) {   // a handful of pairs chip-wide survive the 14-dim screen
            #pragma unroll 1
            while (fmask) {
                int b = __ffs(fmask) - 1;
                fmask &= fmask - 1;
                int cb = b >> 1, rb = b & 1;
                int gib = row0 + r0 + rb * 16 + g;
                int gjb = col0 + c0 + cb * 8 + t * 2;
                #pragma unroll 1
                for (int q = 0; q < 4; ++q) {
                    int gi = gib + (q >> 1) * 8;
                    int gj = gjb + (q & 1);
                    if (gi < n0 && gj < n1) lsum += rare_pair(features, gi, gj);
                }
            }
        }
        __syncthreads();   // before next tile overwrites sm.c.A/B
    }

    // ================= phase 3: reduce + ticket finalize =====================
    lsum = warp_sum(lsum);
    if (lane == 0) sm.c.redw[wid] = lsum;
    __syncthreads();
    if (tid == 0) {
        float s = 0.0f;
        #pragma unroll
        for (int w = 0; w < 8; ++w) s += sm.c.redw[w];
        if (s != 0.0f) atomicAdd(&d_cross, (double)s);
        __threadfence();
        sm.c.ticket = atomicAdd(&d_done, 1u);
    }
    __syncthreads();

    if (sm.c.ticket == GRID - 1) {
        if (tid == 0) __threadfence();
        __syncthreads();

        double pf = 0.0, pg = 0.0, p0 = 0.0, p1 = 0.0;
        #pragma unroll
        for (int k = 0; k < PART_VBLOCKS / 256; ++k) {
            float4 p = d_part[tid + k * 256];
            pf += p.x; pg += p.y; p0 += p.z; p1 += p.w;
        }
        pf = warp_sum_d(pf); pg = warp_sum_d(pg);
        p0 = warp_sum_d(p0); p1 = warp_sum_d(p1);
        if (lane == 0) {
            sm.c.sd[0][wid] = pf; sm.c.sd[1][wid] = pg;
            sm.c.sd[2][wid] = p0; sm.c.sd[3][wid] = p1;
        }

        int cls = tid >> 7, comp = tid & 127;
        double v = (double)d_vsum[cls][comp];
        sm.c.s[tid] = v * v;
        __syncthreads();
        for (int st = 64; st > 0; st >>= 1) {
            if (comp < st) sm.c.s[tid] += sm.c.s[tid + st];
            __syncthreads();
        }
        if (tid == 0) {
            double focal_s = 0.0, graph_s = 0.0, sn0 = 0.0, sn1 = 0.0;
            #pragma unroll
            for (int w = 0; w < 8; ++w) {
                focal_s += sm.c.sd[0][w]; graph_s += sm.c.sd[1][w];
                sn0 += sm.c.sd[2][w]; sn1 += sm.c.sd[3][w];
            }
            double vn0 = sm.c.s[0], vn1 = sm.c.s[128];
            double dn0 = (double)n0, dn1 = (double)n1;
            double same = 2.0 * (dn0 * sn0 - vn0) + 2.0 * (dn1 * sn1 - vn1);
            double NN = (double)N_ROWS * (double)N_ROWS;
            double contrast = (same + 2.0 * d_cross) / NN;
            double focal = focal_s / (double)N_ROWS;
            double graph = 0.1 * graph_s / (double)(N_ROWS - 1);
            out[0] = (float)(focal + contrast + graph);
            d_cnt64 = 0ull;
            d_cross = 0.0;
            d_done  = 0u;
            d_sync1 = 0u;
        }
        d_vsum[cls][comp] = 0.0f;
    }
}

// ---------------- launch ----------------
extern "C" void kernel_launch(void* const* d_in, const int* in_sizes, int n_in,
                              void* d_out, int out_size) {
    const float* preds    = (const float*)d_in[0];
    const float* targets  = (const float*)d_in[1];
    const float* features = (const float*)d_in[2];
    const float* gfeat    = (const float*)d_in[3];
    float* out = (float*)d_out;

    fused_kernel<<<GRID, 256>>>(preds, targets, features, gfeat, out);
}